// round 10
// baseline (speedup 1.0000x reference)
#include <cuda_runtime.h>
#include <cuda_fp16.h>
#include <cstdint>
#include <cstddef>

// ---------------- problem constants ----------------
#define BT_N   4096      // B*T
#define F_DIM  256
#define GV     16384     // G*V
#define V_DIM  8192
#define DG     8
#define KK     768       // 3 * F_DIM  (fp16-split GEMM packed along K)

// ---------------- scratch (device globals; no runtime allocation) ----------------
__device__ __half g_E[(size_t)BT_N * GV];               // 134 MB: exp(h) fp16 for marginal
__device__ float  g_part[(size_t)BT_N * 128 * 16];      // 33.5 MB per-(row,tile) partials
__device__ __half g_Asplit[(size_t)BT_N * KK];          // [xh | xh | xl]
__device__ __half g_Bsplit[(size_t)GV   * KK];          // [Wh | Wl | Wh]
__device__ float  g_R[BT_N * 2];                        // mask*inv_msum/Z per (bt,g)
__device__ float  g_marg[GV];                           // marginal accumulator
__device__ float  g_inv_msum;

// ---------------- FFMA log (final kernel) + exp ----------------
__device__ __forceinline__ float my_logf(float a) {
    float m, r, s, t, i, f;
    int e;
    e = (__float_as_int(a) - 0x3f2aaaab) & 0xff800000;
    m = __int_as_float(__float_as_int(a) - e);
    i = (float)e * 1.19209290e-7f;
    f = m - 1.0f;
    s = f * f;
    r = -0.130310059f;
    t =  0.140869141f;
    r = fmaf(r, s, -0.121483512f);
    t = fmaf(t, s,  0.139814854f);
    r = fmaf(r, s, -0.166846126f);
    t = fmaf(t, s,  0.200120345f);
    r = fmaf(r, s, -0.249996200f);
    r = fmaf(t, f, r);
    r = fmaf(r, f,  0.333331972f);
    r = fmaf(r, f, -0.500000000f);
    r = fmaf(r, s, f);
    r = fmaf(i, 0.693147182f, r);
    return r;
}

__device__ __forceinline__ float my_expf(float a) {
    float f, r, j;
    int i;
    j = fmaf(1.442695041f, a, 12582912.f) - 12582912.f;
    f = fmaf(j, -6.93145752e-1f, a);
    f = fmaf(j, -1.42860677e-6f, f);
    i = (int)j;
    r = 1.37805939e-3f;
    r = fmaf(r, f, 8.37312452e-3f);
    r = fmaf(r, f, 4.16695364e-2f);
    r = fmaf(r, f, 1.66664720e-1f);
    r = fmaf(r, f, 4.99999851e-1f);
    r = fmaf(r, f, 1.00000000e+0f);
    r = fmaf(r, f, 1.00000000e+0f);
    r = __int_as_float(__float_as_int(r) + (i << 23));
    return r;
}

// inner = -log(u); hybrid: MUFU for u<0.875, exact-f log1p Taylor for u>=0.875.
__device__ __forceinline__ float neg_log_u(float uu) {
    uu = fmaxf(uu, 1.17549435e-38f);
    float inner_m = -__logf(uu);
    float f = uu - 1.0f;                       // exact for uu >= 0.5 (Sterbenz)
    float q = fmaf(f, -0.125f, 0.14285714f);   // log1p Taylor deg 7
    q = fmaf(q, f, -0.16666667f);
    q = fmaf(q, f,  0.20f);
    q = fmaf(q, f, -0.25f);
    q = fmaf(q, f,  0.33333333f);
    q = fmaf(q, f, -0.5f);
    q = fmaf(q, f,  1.0f);
    float inner_p = -(f * q);
    return (uu >= 0.875f) ? inner_p : inner_m;
}

// ---------------- prep kernels ----------------
__global__ void prep_split_w(const float* __restrict__ W) {
    int idx = blockIdx.x * blockDim.x + threadIdx.x;
    if (idx >= GV * F_DIM) return;
    int n = idx >> 8, k = idx & 255;
    float w = W[idx];
    __half hi = __float2half_rn(w);
    __half lo = __float2half_rn(w - __half2float(hi));
    size_t base = (size_t)n * KK;
    g_Bsplit[base + k]        = hi;
    g_Bsplit[base + 256 + k]  = lo;
    g_Bsplit[base + 512 + k]  = hi;
}

__global__ void prep_split_x(const float* __restrict__ X) {
    int idx = blockIdx.x * blockDim.x + threadIdx.x;
    if (idx >= BT_N * F_DIM) return;
    int n = idx >> 8, k = idx & 255;
    float x = X[idx];
    __half hi = __float2half_rn(x);
    __half lo = __float2half_rn(x - __half2float(hi));
    size_t base = (size_t)n * KK;
    g_Asplit[base + k]        = hi;
    g_Asplit[base + 256 + k]  = hi;
    g_Asplit[base + 512 + k]  = lo;
}

__global__ void prep_misc(const int* __restrict__ mask) {
    int t = threadIdx.x;
    for (int i = t; i < GV; i += 256) g_marg[i] = 0.f;
    int s = 0;
    for (int i = t; i < BT_N; i += 256) s += mask[i];
    __shared__ int sm[256];
    sm[t] = s; __syncthreads();
    for (int o = 128; o; o >>= 1) { if (t < o) sm[t] += sm[t + o]; __syncthreads(); }
    if (t == 0) g_inv_msum = 1.0f / (float)sm[0];
}

// ---------------- fused GEMM + epilogue ----------------
// Block tile 128x128, 4 warps, warp tile 64x64, BK=64, 3 stages, 2 CTAs/SM.
// Epilogue v3: h staged to smem; column-parallel coalesced U/e/g_E phase;
// row-parallel partials phase with sh from fp16 e in smem.
#define BM 128
#define BN 128
#define BK 64
#define STAGES 3
#define A_BYTES  (BM * BK * 2)          // 16384
#define STG_BYTES (2 * A_BYTES)         // 32768
#define YSTRIDE 133                      // floats; bank stride 5 (odd) -> conflict-free
#define ESTRIDE 130                      // halfs;  4B-bank stride 65 (odd) -> conflict-free
#define YSM_BYTES (128 * YSTRIDE * 4)    // 68096
#define ESM_BYTES (128 * ESTRIDE * 2)    // 33280
#define GEMM_SMEM (YSM_BYTES + ESM_BYTES)  // 101376 (> 3*STG_BYTES = 98304)

__global__ void __launch_bounds__(128, 2) gemm_kernel(
    const float* __restrict__ bias, const float* __restrict__ U,
    const float* __restrict__ emb)
{
    extern __shared__ __align__(128) char smem[];
    int tid  = threadIdx.x;
    int lane = tid & 31, warp = tid >> 5;
    int wm = warp >> 1, wn = warp & 1;        // 2 x 2 warp grid, warp tile 64x64
    int bm = blockIdx.y, bn = blockIdx.x;
    const __half* gA = g_Asplit + (size_t)bm * BM * KK;
    const __half* gB = g_Bsplit + (size_t)bn * BN * KK;

    auto load_stage = [&](int s, int kt) {
        int k0 = kt * BK;
        char* sa = smem + s * STG_BYTES;
        char* sb = sa + A_BYTES;
        #pragma unroll
        for (int i = 0; i < 8; i++) {
            int idx = tid + 128 * i;       // 0..1023
            int row = idx >> 3, c16 = idx & 7;
            int pc  = c16 ^ (row & 7);
            uint32_t da = (uint32_t)__cvta_generic_to_shared(sa + row * 128 + pc * 16);
            asm volatile("cp.async.cg.shared.global [%0], [%1], 16;\n"
                :: "r"(da), "l"(gA + (size_t)row * KK + k0 + c16 * 8));
            uint32_t db = (uint32_t)__cvta_generic_to_shared(sb + row * 128 + pc * 16);
            asm volatile("cp.async.cg.shared.global [%0], [%1], 16;\n"
                :: "r"(db), "l"(gB + (size_t)row * KK + k0 + c16 * 8));
        }
    };

    float acc[4][8][4];
    #pragma unroll
    for (int a = 0; a < 4; a++)
        #pragma unroll
        for (int b = 0; b < 8; b++)
            #pragma unroll
            for (int c = 0; c < 4; c++) acc[a][b][c] = 0.f;

    const int NKT = KK / BK;  // 12
    #pragma unroll
    for (int kt = 0; kt < STAGES - 1; kt++) {
        load_stage(kt, kt);
        asm volatile("cp.async.commit_group;\n");
    }

    #pragma unroll 1
    for (int kt = 0; kt < NKT; kt++) {
        asm volatile("cp.async.wait_group 1;\n");
        __syncthreads();
        int pf = kt + STAGES - 1;
        if (pf < NKT) load_stage(pf % STAGES, pf);
        asm volatile("cp.async.commit_group;\n");

        int s = kt % STAGES;
        const char* sa = smem + s * STG_BYTES;
        const char* sb = sa + A_BYTES;
        #pragma unroll
        for (int kk = 0; kk < 4; kk++) {
            uint32_t a[4][4], b[8][2];
            int c16 = kk * 2 + (lane >> 4);
            #pragma unroll
            for (int mt = 0; mt < 4; mt++) {
                int row = wm * 64 + mt * 16 + (lane & 15);
                int pc  = c16 ^ (row & 7);
                uint32_t addr = (uint32_t)__cvta_generic_to_shared(sa + row * 128 + pc * 16);
                asm volatile("ldmatrix.sync.aligned.m8n8.x4.shared.b16 {%0,%1,%2,%3}, [%4];\n"
                    : "=r"(a[mt][0]), "=r"(a[mt][1]), "=r"(a[mt][2]), "=r"(a[mt][3]) : "r"(addr));
            }
            #pragma unroll
            for (int nb = 0; nb < 4; nb++) {
                int row = wn * 64 + nb * 16 + (lane & 15);
                int pc  = c16 ^ (row & 7);
                uint32_t addr = (uint32_t)__cvta_generic_to_shared(sb + row * 128 + pc * 16);
                uint32_t r0, r1, r2, r3;
                asm volatile("ldmatrix.sync.aligned.m8n8.x4.shared.b16 {%0,%1,%2,%3}, [%4];\n"
                    : "=r"(r0), "=r"(r1), "=r"(r2), "=r"(r3) : "r"(addr));
                b[nb * 2][0]     = r0; b[nb * 2 + 1][0] = r1;
                b[nb * 2][1]     = r2; b[nb * 2 + 1][1] = r3;
            }
            #pragma unroll
            for (int mt = 0; mt < 4; mt++)
                #pragma unroll
                for (int nt = 0; nt < 8; nt++) {
                    asm volatile("mma.sync.aligned.m16n8k16.row.col.f32.f16.f16.f32 "
                        "{%0,%1,%2,%3}, {%4,%5,%6,%7}, {%8,%9}, {%0,%1,%2,%3};\n"
                        : "+f"(acc[mt][nt][0]), "+f"(acc[mt][nt][1]),
                          "+f"(acc[mt][nt][2]), "+f"(acc[mt][nt][3])
                        : "r"(a[mt][0]), "r"(a[mt][1]), "r"(a[mt][2]), "r"(a[mt][3]),
                          "r"(b[nt][0]), "r"(b[nt][1]));
                }
        }
    }

    // ---- epilogue v3 ----
    asm volatile("cp.async.wait_group 0;\n");
    __syncthreads();
    float*  ysm = (float*)smem;                     // [128][YSTRIDE] h then ey
    __half* e16 = (__half*)(smem + YSM_BYTES);      // [128][ESTRIDE] e (fp16)

    const int g  = bn >> 6;
    const int v0 = (bn & 63) * 128;

    // phase 0: accumulators (+bias) -> smem
    {
        float2 bb[8];
        #pragma unroll
        for (int nt = 0; nt < 8; nt++) {
            int n = bn * BN + wn * 64 + nt * 8 + (lane & 3) * 2;
            bb[nt] = *(const float2*)(bias + n);
        }
        #pragma unroll
        for (int mt = 0; mt < 4; mt++) {
            #pragma unroll
            for (int ch = 0; ch < 2; ch++) {
                int row_l = wm * 64 + mt * 16 + (lane >> 2) + ch * 8;
                #pragma unroll
                for (int nt = 0; nt < 8; nt++) {
                    int col_l = wn * 64 + nt * 8 + (lane & 3) * 2;
                    ysm[row_l * YSTRIDE + col_l]     = acc[mt][nt][ch * 2 + 0] + bb[nt].x;
                    ysm[row_l * YSTRIDE + col_l + 1] = acc[mt][nt][ch * 2 + 1] + bb[nt].y;
                }
            }
        }
    }
    __syncthreads();

    // phase 1: column-parallel, fully coalesced. thread tid = column.
    {
        size_t gbase = (size_t)(bm * BM) * GV + bn * BN + tid;
        const float* Up = U + gbase;
        __half* Ep = g_E + gbase;
        float* yp = ysm + tid;
        __half* ep = e16 + tid;
        #pragma unroll 4
        for (int i = 0; i < 128; i++) {
            float h = yp[0];
            float e = __expf(h);
            float uu = Up[0];
            float ey = __fdividef(e, neg_log_u(uu));
            yp[0] = ey;
            __half eh = __float2half_rn(e);
            ep[0] = eh;
            Ep[0] = eh;
            yp += YSTRIDE; ep += ESTRIDE; Up += GV; Ep += GV;
        }
    }
    __syncthreads();

    // phase 2: row-parallel partials. thread tid = row.
    {
        int row_l = tid;
        int m = bm * BM + row_l;
        const float*  yr = ysm + row_l * YSTRIDE;
        const __half2* er = (const __half2*)(e16 + row_l * ESTRIDE);
        float sy = 0.f, sh = 0.f, myv = -1e30f;
        int bi = 0;
        float cv[8] = {0, 0, 0, 0, 0, 0, 0, 0};
        const float4* eb = (const float4*)(emb + ((size_t)g * V_DIM + v0) * DG);
        #pragma unroll 2
        for (int j2 = 0; j2 < 64; j2++) {
            float2 ee = __half22float2(er[j2]);
            sh += ee.x + ee.y;
            #pragma unroll
            for (int q = 0; q < 2; q++) {
                int j = j2 * 2 + q;
                float ey = yr[j];
                sy += ey;
                float4 e0 = eb[j * 2], e1 = eb[j * 2 + 1];
                cv[0] = fmaf(ey, e0.x, cv[0]); cv[1] = fmaf(ey, e0.y, cv[1]);
                cv[2] = fmaf(ey, e0.z, cv[2]); cv[3] = fmaf(ey, e0.w, cv[3]);
                cv[4] = fmaf(ey, e1.x, cv[4]); cv[5] = fmaf(ey, e1.y, cv[5]);
                cv[6] = fmaf(ey, e1.z, cv[6]); cv[7] = fmaf(ey, e1.w, cv[7]);
                if (ey > myv) { myv = ey; bi = j; }
            }
        }
        float* P = g_part + ((size_t)m * 128 + bn) * 16;
        ((float4*)P)[0] = make_float4(sy, myv, (float)(v0 + bi), sh);
        ((float4*)P)[1] = make_float4(cv[0], cv[1], cv[2], cv[3]);
        ((float4*)P)[2] = make_float4(cv[4], cv[5], cv[6], cv[7]);
    }
}

// ---------------- combine: reduce 64 tile-partials per (bt,g) ----------------
__global__ void __launch_bounds__(32) combine_kernel(
    const int* __restrict__ mask, float* __restrict__ out)
{
    int r = blockIdx.x;            // 0..8191
    int bt = r >> 1, gg = r & 1;
    int lane = threadIdx.x;
    const float* Pa = g_part + (((size_t)bt * 128) + gg * 64 + lane) * 16;
    const float* Pb = Pa + 32 * 16;
    float4 a0 = ((const float4*)Pa)[0], a1 = ((const float4*)Pa)[1], a2 = ((const float4*)Pa)[2];
    float4 b0 = ((const float4*)Pb)[0], b1 = ((const float4*)Pb)[1], b2 = ((const float4*)Pb)[2];
    float sy = a0.x + b0.x;
    float sh = a0.w + b0.w;
    float my = a0.y, vx = a0.z;
    if (b0.y > my || (b0.y == my && b0.z < vx)) { my = b0.y; vx = b0.z; }
    float cv[8];
    cv[0] = a1.x + b1.x; cv[1] = a1.y + b1.y; cv[2] = a1.z + b1.z; cv[3] = a1.w + b1.w;
    cv[4] = a2.x + b2.x; cv[5] = a2.y + b2.y; cv[6] = a2.z + b2.z; cv[7] = a2.w + b2.w;
    #pragma unroll
    for (int o = 16; o; o >>= 1) {
        sy += __shfl_xor_sync(0xffffffffu, sy, o);
        sh += __shfl_xor_sync(0xffffffffu, sh, o);
        float omy = __shfl_xor_sync(0xffffffffu, my, o);
        float ovx = __shfl_xor_sync(0xffffffffu, vx, o);
        if (omy > my || (omy == my && ovx < vx)) { my = omy; vx = ovx; }
        #pragma unroll
        for (int d = 0; d < 8; d++) cv[d] += __shfl_xor_sync(0xffffffffu, cv[d], o);
    }
    if (lane == 0) {
        float is = 1.f / sy;
        #pragma unroll
        for (int d = 0; d < 8; d++) out[bt * 16 + gg * 8 + d] = cv[d] * is;
        out[65537 + r] = vx;                                   // targets_idx
        g_R[r] = mask[bt] ? (g_inv_msum / sh) : 0.f;
    }
}

// ---------------- marginal column reduction (fp16 e, half2) ----------------
__global__ void __launch_bounds__(256) marg_kernel() {
    int c2 = blockIdx.x * 256 + threadIdx.x;   // 0..8191 column pairs
    int c  = c2 * 2;
    int g  = c >> 13;
    int bt0 = blockIdx.y * 256;
    float ax = 0.f, ay = 0.f;
    const __half2* Ep = (const __half2*)(g_E + (size_t)bt0 * GV + c);
    const float*   Rp = g_R + bt0 * 2 + g;
    #pragma unroll 4
    for (int i = 0; i < 256; ++i) {
        float2 e2 = __half22float2(*Ep);
        float r = *Rp;
        ax = fmaf(r, e2.x, ax);
        ay = fmaf(r, e2.y, ay);
        Ep += GV / 2;
        Rp += 2;
    }
    atomicAdd(&g_marg[c], ax);
    atomicAdd(&g_marg[c + 1], ay);
}

// ---------------- perplexity ----------------
__global__ void __launch_bounds__(256) final_kernel(float* __restrict__ out) {
    int t = threadIdx.x;
    float s0 = 0.f, s1v = 0.f;
    for (int c = t; c < V_DIM; c += 256) {
        float m = g_marg[c];
        s0 += m * my_logf(m + 1e-7f);
    }
    for (int c = V_DIM + t; c < GV; c += 256) {
        float m = g_marg[c];
        s1v += m * my_logf(m + 1e-7f);
    }
    __shared__ float sa[256], sb[256];
    sa[t] = s0; sb[t] = s1v; __syncthreads();
    for (int o = 128; o; o >>= 1) {
        if (t < o) { sa[t] += sa[t + o]; sb[t] += sb[t + o]; }
        __syncthreads();
    }
    if (t == 0) out[65536] = my_expf(-sa[0]) + my_expf(-sb[0]);
}

// ---------------- launch ----------------
extern "C" void kernel_launch(void* const* d_in, const int* in_sizes, int n_in,
                              void* d_out, int out_size) {
    const float* x    = (const float*)d_in[0];   // [8,512,256]
    const float* u    = (const float*)d_in[1];   // [8192, 8192]
    const float* emb  = (const float*)d_in[2];   // [1, 16384, 8]
    const float* W    = (const float*)d_in[3];   // [16384, 256]
    const float* bias = (const float*)d_in[4];   // [16384]
    const int*   mask = (const int*)d_in[5];     // [8,512]
    float* out = (float*)d_out;

    cudaFuncSetAttribute(gemm_kernel, cudaFuncAttributeMaxDynamicSharedMemorySize, GEMM_SMEM);

    prep_split_w<<<(GV * F_DIM + 255) / 256, 256>>>(W);
    prep_split_x<<<(BT_N * F_DIM + 255) / 256, 256>>>(x);
    prep_misc<<<1, 256>>>(mask);

    dim3 ggrid(GV / BN, BT_N / BM);   // (128, 32)
    gemm_kernel<<<ggrid, 128, GEMM_SMEM>>>(bias, u, emb);

    combine_kernel<<<BT_N * 2, 32>>>(mask, out);

    dim3 mgrid(GV / 512, 16);
    marg_kernel<<<mgrid, 256>>>();

    final_kernel<<<1, 256>>>(out);
}

// round 11
// speedup vs baseline: 1.5133x; 1.5133x over previous
#include <cuda_runtime.h>
#include <cuda_fp16.h>
#include <cstdint>
#include <cstddef>

// ---------------- problem constants ----------------
#define BT_N   4096      // B*T
#define F_DIM  256
#define GV     16384     // G*V
#define V_DIM  8192
#define DG     8
#define KK     768       // 3 * F_DIM  (fp16-split GEMM packed along K)

// ---------------- scratch (device globals; no runtime allocation) ----------------
__device__ __half g_E[(size_t)BT_N * GV];               // 134 MB: exp(h) fp16 for marginal
__device__ float  g_part[(size_t)BT_N * 128 * 16];      // 33.5 MB per-(row,tile) partials
__device__ __half g_Asplit[(size_t)BT_N * KK];          // [xh | xh | xl]
__device__ __half g_Bsplit[(size_t)GV   * KK];          // [Wh | Wl | Wh]
__device__ float  g_R[BT_N * 2];                        // mask*inv_msum/Z per (bt,g)
__device__ float  g_marg[GV];                           // marginal accumulator
__device__ float  g_inv_msum;

// ---------------- FFMA log (final kernel) + exp ----------------
__device__ __forceinline__ float my_logf(float a) {
    float m, r, s, t, i, f;
    int e;
    e = (__float_as_int(a) - 0x3f2aaaab) & 0xff800000;
    m = __int_as_float(__float_as_int(a) - e);
    i = (float)e * 1.19209290e-7f;
    f = m - 1.0f;
    s = f * f;
    r = -0.130310059f;
    t =  0.140869141f;
    r = fmaf(r, s, -0.121483512f);
    t = fmaf(t, s,  0.139814854f);
    r = fmaf(r, s, -0.166846126f);
    t = fmaf(t, s,  0.200120345f);
    r = fmaf(r, s, -0.249996200f);
    r = fmaf(t, f, r);
    r = fmaf(r, f,  0.333331972f);
    r = fmaf(r, f, -0.500000000f);
    r = fmaf(r, s, f);
    r = fmaf(i, 0.693147182f, r);
    return r;
}

__device__ __forceinline__ float my_expf(float a) {
    float f, r, j;
    int i;
    j = fmaf(1.442695041f, a, 12582912.f) - 12582912.f;
    f = fmaf(j, -6.93145752e-1f, a);
    f = fmaf(j, -1.42860677e-6f, f);
    i = (int)j;
    r = 1.37805939e-3f;
    r = fmaf(r, f, 8.37312452e-3f);
    r = fmaf(r, f, 4.16695364e-2f);
    r = fmaf(r, f, 1.66664720e-1f);
    r = fmaf(r, f, 4.99999851e-1f);
    r = fmaf(r, f, 1.00000000e+0f);
    r = fmaf(r, f, 1.00000000e+0f);
    r = __int_as_float(__float_as_int(r) + (i << 23));
    return r;
}

// inner = -log(u); hybrid: MUFU for u<0.875, exact-f log1p Taylor for u>=0.875.
__device__ __forceinline__ float neg_log_u(float uu) {
    uu = fmaxf(uu, 1.17549435e-38f);
    float inner_m = -__logf(uu);
    float f = uu - 1.0f;                       // exact for uu >= 0.5 (Sterbenz)
    float q = fmaf(f, -0.125f, 0.14285714f);   // log1p Taylor deg 7
    q = fmaf(q, f, -0.16666667f);
    q = fmaf(q, f,  0.20f);
    q = fmaf(q, f, -0.25f);
    q = fmaf(q, f,  0.33333333f);
    q = fmaf(q, f, -0.5f);
    q = fmaf(q, f,  1.0f);
    float inner_p = -(f * q);
    return (uu >= 0.875f) ? inner_p : inner_m;
}

// ---------------- prep kernels ----------------
__global__ void prep_split_w(const float* __restrict__ W) {
    int idx = blockIdx.x * blockDim.x + threadIdx.x;
    if (idx >= GV * F_DIM) return;
    int n = idx >> 8, k = idx & 255;
    float w = W[idx];
    __half hi = __float2half_rn(w);
    __half lo = __float2half_rn(w - __half2float(hi));
    size_t base = (size_t)n * KK;
    g_Bsplit[base + k]        = hi;
    g_Bsplit[base + 256 + k]  = lo;
    g_Bsplit[base + 512 + k]  = hi;
}

__global__ void prep_split_x(const float* __restrict__ X) {
    int idx = blockIdx.x * blockDim.x + threadIdx.x;
    if (idx >= BT_N * F_DIM) return;
    int n = idx >> 8, k = idx & 255;
    float x = X[idx];
    __half hi = __float2half_rn(x);
    __half lo = __float2half_rn(x - __half2float(hi));
    size_t base = (size_t)n * KK;
    g_Asplit[base + k]        = hi;
    g_Asplit[base + 256 + k]  = hi;
    g_Asplit[base + 512 + k]  = lo;
}

__global__ void prep_misc(const int* __restrict__ mask) {
    int t = threadIdx.x;
    for (int i = t; i < GV; i += 256) g_marg[i] = 0.f;
    int s = 0;
    for (int i = t; i < BT_N; i += 256) s += mask[i];
    __shared__ int sm[256];
    sm[t] = s; __syncthreads();
    for (int o = 128; o; o >>= 1) { if (t < o) sm[t] += sm[t + o]; __syncthreads(); }
    if (t == 0) g_inv_msum = 1.0f / (float)sm[0];
}

// ---------------- fused GEMM + epilogue ----------------
// Block tile 128x128, 4 warps, warp tile 64x64, BK=64, 3 stages, 2 CTAs/SM.
// Epilogue v4: U prefetched into freed smem stages during mainloop tail;
// fragment-layout phase reads U from smem, writes ey in place; row phase
// reads ey rows from smem. sh via quad-shuffle reduction.
#define BM 128
#define BN 128
#define BK 64
#define STAGES 3
#define A_BYTES  (BM * BK * 2)          // 16384
#define STG_BYTES (2 * A_BYTES)         // 32768
#define GEMM_SMEM (STAGES * STG_BYTES)  // 98304

// swizzled byte offset of float2 (row r, col-pair c2) within the 64KB U region
#define USWZ(r, c2) ((r) * 512 + ((((c2) >> 1) ^ ((r) & 7)) << 4) + (((c2) & 1) << 3))

__global__ void __launch_bounds__(128, 2) gemm_kernel(
    const float* __restrict__ bias, const float* __restrict__ U,
    const float* __restrict__ emb)
{
    extern __shared__ __align__(128) char smem[];
    int tid  = threadIdx.x;
    int lane = tid & 31, warp = tid >> 5;
    int wm = warp >> 1, wn = warp & 1;        // 2 x 2 warp grid, warp tile 64x64
    int bm = blockIdx.y, bn = blockIdx.x;
    const __half* gA = g_Asplit + (size_t)bm * BM * KK;
    const __half* gB = g_Bsplit + (size_t)bn * BN * KK;

    auto load_stage = [&](int s, int kt) {
        int k0 = kt * BK;
        char* sa = smem + s * STG_BYTES;
        char* sb = sa + A_BYTES;
        #pragma unroll
        for (int i = 0; i < 8; i++) {
            int idx = tid + 128 * i;       // 0..1023
            int row = idx >> 3, c16 = idx & 7;
            int pc  = c16 ^ (row & 7);
            uint32_t da = (uint32_t)__cvta_generic_to_shared(sa + row * 128 + pc * 16);
            asm volatile("cp.async.cg.shared.global [%0], [%1], 16;\n"
                :: "r"(da), "l"(gA + (size_t)row * KK + k0 + c16 * 8));
            uint32_t db = (uint32_t)__cvta_generic_to_shared(sb + row * 128 + pc * 16);
            asm volatile("cp.async.cg.shared.global [%0], [%1], 16;\n"
                :: "r"(db), "l"(gB + (size_t)row * KK + k0 + c16 * 8));
        }
    };

    // prefetch half of the U tile (64 rows x 128 cols fp32 = 32KB) into a freed stage
    auto load_u_half = [&](int half) {
        const float* Ub = U + (size_t)(bm * BM + half * 64) * GV + bn * BN;
        char* dstbase = smem + half * STG_BYTES;   // stage 'half' (0 or 1)
        #pragma unroll
        for (int i = 0; i < 16; i++) {
            int idx = tid + 128 * i;       // 0..2047 chunks
            int rr = idx >> 5, cc = idx & 31;   // rr 0..63 (local), cc chunk 0..31
            uint32_t d = (uint32_t)__cvta_generic_to_shared(
                dstbase + rr * 512 + ((cc ^ (rr & 7)) << 4));
            asm volatile("cp.async.cg.shared.global [%0], [%1], 16;\n"
                :: "r"(d), "l"(Ub + (size_t)rr * GV + cc * 4));
        }
    };

    float acc[4][8][4];
    #pragma unroll
    for (int a = 0; a < 4; a++)
        #pragma unroll
        for (int b = 0; b < 8; b++)
            #pragma unroll
            for (int c = 0; c < 4; c++) acc[a][b][c] = 0.f;

    const int NKT = KK / BK;  // 12
    #pragma unroll
    for (int kt = 0; kt < STAGES - 1; kt++) {
        load_stage(kt, kt);
        asm volatile("cp.async.commit_group;\n");
    }

    #pragma unroll 1
    for (int kt = 0; kt < NKT; kt++) {
        asm volatile("cp.async.wait_group 1;\n");
        __syncthreads();
        int pf = kt + STAGES - 1;
        if (pf < NKT) {
            load_stage(pf % STAGES, pf);
        } else {
            // pf==12 (kt==10): stage0 just freed -> U rows 0-63
            // pf==13 (kt==11): stage1 just freed -> U rows 64-127
            load_u_half(pf - NKT);
        }
        asm volatile("cp.async.commit_group;\n");

        int s = kt % STAGES;
        const char* sa = smem + s * STG_BYTES;
        const char* sb = sa + A_BYTES;
        #pragma unroll
        for (int kk = 0; kk < 4; kk++) {
            uint32_t a[4][4], b[8][2];
            int c16 = kk * 2 + (lane >> 4);
            #pragma unroll
            for (int mt = 0; mt < 4; mt++) {
                int row = wm * 64 + mt * 16 + (lane & 15);
                int pc  = c16 ^ (row & 7);
                uint32_t addr = (uint32_t)__cvta_generic_to_shared(sa + row * 128 + pc * 16);
                asm volatile("ldmatrix.sync.aligned.m8n8.x4.shared.b16 {%0,%1,%2,%3}, [%4];\n"
                    : "=r"(a[mt][0]), "=r"(a[mt][1]), "=r"(a[mt][2]), "=r"(a[mt][3]) : "r"(addr));
            }
            #pragma unroll
            for (int nb = 0; nb < 4; nb++) {
                int row = wn * 64 + nb * 16 + (lane & 15);
                int pc  = c16 ^ (row & 7);
                uint32_t addr = (uint32_t)__cvta_generic_to_shared(sb + row * 128 + pc * 16);
                uint32_t r0, r1, r2, r3;
                asm volatile("ldmatrix.sync.aligned.m8n8.x4.shared.b16 {%0,%1,%2,%3}, [%4];\n"
                    : "=r"(r0), "=r"(r1), "=r"(r2), "=r"(r3) : "r"(addr));
                b[nb * 2][0]     = r0; b[nb * 2 + 1][0] = r1;
                b[nb * 2][1]     = r2; b[nb * 2 + 1][1] = r3;
            }
            #pragma unroll
            for (int mt = 0; mt < 4; mt++)
                #pragma unroll
                for (int nt = 0; nt < 8; nt++) {
                    asm volatile("mma.sync.aligned.m16n8k16.row.col.f32.f16.f16.f32 "
                        "{%0,%1,%2,%3}, {%4,%5,%6,%7}, {%8,%9}, {%0,%1,%2,%3};\n"
                        : "+f"(acc[mt][nt][0]), "+f"(acc[mt][nt][1]),
                          "+f"(acc[mt][nt][2]), "+f"(acc[mt][nt][3])
                        : "r"(a[mt][0]), "r"(a[mt][1]), "r"(a[mt][2]), "r"(a[mt][3]),
                          "r"(b[nt][0]), "r"(b[nt][1]));
                }
        }
    }

    // ---- epilogue v4 ----
    asm volatile("cp.async.wait_group 0;\n");
    __syncthreads();                              // U tile resident in stages 0-1
    float* shsm = (float*)(smem + 2 * STG_BYTES); // [128][2] in dead stage2

    const int g  = bn >> 6;
    const int v0 = (bn & 63) * 128;

    // bias for this thread's 16 columns
    float2 bb[8];
    #pragma unroll
    for (int nt = 0; nt < 8; nt++) {
        int n = bn * BN + wn * 64 + nt * 8 + (lane & 3) * 2;
        bb[nt] = *(const float2*)(bias + n);
    }

    float shp[8];
    #pragma unroll
    for (int i = 0; i < 8; i++) shp[i] = 0.f;

    // phase 1: fragment layout; U from smem, ey in place, e -> g_E
    #pragma unroll
    for (int mt = 0; mt < 4; mt++) {
        #pragma unroll
        for (int ch = 0; ch < 2; ch++) {
            int row_l = wm * 64 + mt * 16 + (lane >> 2) + ch * 8;
            size_t gb = (size_t)(bm * BM + row_l) * GV + bn * BN;
            #pragma unroll
            for (int nt = 0; nt < 8; nt++) {
                int col2 = wn * 32 + nt * 4 + (lane & 3);   // float2 index 0..63
                float* up = (float*)(smem + USWZ(row_l, col2));
                float2 uv = *(float2*)up;
                float h0 = acc[mt][nt][ch * 2 + 0] + bb[nt].x;
                float h1 = acc[mt][nt][ch * 2 + 1] + bb[nt].y;
                float e0 = __expf(h0), e1 = __expf(h1);
                shp[mt * 2 + ch] += e0 + e1;
                *(__half2*)(&g_E[gb + col2 * 2]) = __floats2half2_rn(e0, e1);
                float ey0 = __fdividef(e0, neg_log_u(uv.x));
                float ey1 = __fdividef(e1, neg_log_u(uv.y));
                *(float2*)up = make_float2(ey0, ey1);
            }
        }
    }
    // quad-reduce Z partials (4 lanes of each quad hold same rows)
    #pragma unroll
    for (int i = 0; i < 8; i++) {
        shp[i] += __shfl_xor_sync(0xffffffffu, shp[i], 1);
        shp[i] += __shfl_xor_sync(0xffffffffu, shp[i], 2);
    }
    if ((lane & 3) == 0) {
        #pragma unroll
        for (int i = 0; i < 8; i++) {
            int mt = i >> 1, ch = i & 1;
            int row_l = wm * 64 + mt * 16 + (lane >> 2) + ch * 8;
            shsm[row_l * 2 + wn] = shp[i];
        }
    }
    __syncthreads();

    // phase 2: row-parallel partials. thread tid = row.
    {
        int row_l = tid;
        int m = bm * BM + row_l;
        float sh = shsm[row_l * 2 + 0] + shsm[row_l * 2 + 1];
        float sy = 0.f, myv = -1e30f;
        int bi = 0;
        float cv[8] = {0, 0, 0, 0, 0, 0, 0, 0};
        const float4* eb = (const float4*)(emb + ((size_t)g * V_DIM + v0) * DG);
        #pragma unroll 4
        for (int j2 = 0; j2 < 64; j2++) {
            float2 eyv = *(const float2*)(smem + USWZ(row_l, j2));
            #pragma unroll
            for (int q = 0; q < 2; q++) {
                int j = j2 * 2 + q;
                float ey = (q == 0) ? eyv.x : eyv.y;
                sy += ey;
                float4 e0 = eb[j * 2], e1 = eb[j * 2 + 1];
                cv[0] = fmaf(ey, e0.x, cv[0]); cv[1] = fmaf(ey, e0.y, cv[1]);
                cv[2] = fmaf(ey, e0.z, cv[2]); cv[3] = fmaf(ey, e0.w, cv[3]);
                cv[4] = fmaf(ey, e1.x, cv[4]); cv[5] = fmaf(ey, e1.y, cv[5]);
                cv[6] = fmaf(ey, e1.z, cv[6]); cv[7] = fmaf(ey, e1.w, cv[7]);
                if (ey > myv) { myv = ey; bi = j; }
            }
        }
        float* P = g_part + ((size_t)m * 128 + bn) * 16;
        ((float4*)P)[0] = make_float4(sy, myv, (float)(v0 + bi), sh);
        ((float4*)P)[1] = make_float4(cv[0], cv[1], cv[2], cv[3]);
        ((float4*)P)[2] = make_float4(cv[4], cv[5], cv[6], cv[7]);
    }
}

// ---------------- combine: reduce 64 tile-partials per (bt,g) ----------------
__global__ void __launch_bounds__(32) combine_kernel(
    const int* __restrict__ mask, float* __restrict__ out)
{
    int r = blockIdx.x;            // 0..8191
    int bt = r >> 1, gg = r & 1;
    int lane = threadIdx.x;
    const float* Pa = g_part + (((size_t)bt * 128) + gg * 64 + lane) * 16;
    const float* Pb = Pa + 32 * 16;
    float4 a0 = ((const float4*)Pa)[0], a1 = ((const float4*)Pa)[1], a2 = ((const float4*)Pa)[2];
    float4 b0 = ((const float4*)Pb)[0], b1 = ((const float4*)Pb)[1], b2 = ((const float4*)Pb)[2];
    float sy = a0.x + b0.x;
    float sh = a0.w + b0.w;
    float my = a0.y, vx = a0.z;
    if (b0.y > my || (b0.y == my && b0.z < vx)) { my = b0.y; vx = b0.z; }
    float cv[8];
    cv[0] = a1.x + b1.x; cv[1] = a1.y + b1.y; cv[2] = a1.z + b1.z; cv[3] = a1.w + b1.w;
    cv[4] = a2.x + b2.x; cv[5] = a2.y + b2.y; cv[6] = a2.z + b2.z; cv[7] = a2.w + b2.w;
    #pragma unroll
    for (int o = 16; o; o >>= 1) {
        sy += __shfl_xor_sync(0xffffffffu, sy, o);
        sh += __shfl_xor_sync(0xffffffffu, sh, o);
        float omy = __shfl_xor_sync(0xffffffffu, my, o);
        float ovx = __shfl_xor_sync(0xffffffffu, vx, o);
        if (omy > my || (omy == my && ovx < vx)) { my = omy; vx = ovx; }
        #pragma unroll
        for (int d = 0; d < 8; d++) cv[d] += __shfl_xor_sync(0xffffffffu, cv[d], o);
    }
    if (lane == 0) {
        float is = 1.f / sy;
        #pragma unroll
        for (int d = 0; d < 8; d++) out[bt * 16 + gg * 8 + d] = cv[d] * is;
        out[65537 + r] = vx;                                   // targets_idx
        g_R[r] = mask[bt] ? (g_inv_msum / sh) : 0.f;
    }
}

// ---------------- marginal column reduction (fp16 e, half2) ----------------
__global__ void __launch_bounds__(256) marg_kernel() {
    int c2 = blockIdx.x * 256 + threadIdx.x;   // 0..8191 column pairs
    int c  = c2 * 2;
    int g  = c >> 13;
    int bt0 = blockIdx.y * 256;
    float ax = 0.f, ay = 0.f;
    const __half2* Ep = (const __half2*)(g_E + (size_t)bt0 * GV + c);
    const float*   Rp = g_R + bt0 * 2 + g;
    #pragma unroll 4
    for (int i = 0; i < 256; ++i) {
        float2 e2 = __half22float2(*Ep);
        float r = *Rp;
        ax = fmaf(r, e2.x, ax);
        ay = fmaf(r, e2.y, ay);
        Ep += GV / 2;
        Rp += 2;
    }
    atomicAdd(&g_marg[c], ax);
    atomicAdd(&g_marg[c + 1], ay);
}

// ---------------- perplexity ----------------
__global__ void __launch_bounds__(256) final_kernel(float* __restrict__ out) {
    int t = threadIdx.x;
    float s0 = 0.f, s1v = 0.f;
    for (int c = t; c < V_DIM; c += 256) {
        float m = g_marg[c];
        s0 += m * my_logf(m + 1e-7f);
    }
    for (int c = V_DIM + t; c < GV; c += 256) {
        float m = g_marg[c];
        s1v += m * my_logf(m + 1e-7f);
    }
    __shared__ float sa[256], sb[256];
    sa[t] = s0; sb[t] = s1v; __syncthreads();
    for (int o = 128; o; o >>= 1) {
        if (t < o) { sa[t] += sa[t + o]; sb[t] += sb[t + o]; }
        __syncthreads();
    }
    if (t == 0) out[65536] = my_expf(-sa[0]) + my_expf(-sb[0]);
}

// ---------------- launch ----------------
extern "C" void kernel_launch(void* const* d_in, const int* in_sizes, int n_in,
                              void* d_out, int out_size) {
    const float* x    = (const float*)d_in[0];   // [8,512,256]
    const float* u    = (const float*)d_in[1];   // [8192, 8192]
    const float* emb  = (const float*)d_in[2];   // [1, 16384, 8]
    const float* W    = (const float*)d_in[3];   // [16384, 256]
    const float* bias = (const float*)d_in[4];   // [16384]
    const int*   mask = (const int*)d_in[5];     // [8,512]
    float* out = (float*)d_out;

    cudaFuncSetAttribute(gemm_kernel, cudaFuncAttributeMaxDynamicSharedMemorySize, GEMM_SMEM);

    prep_split_w<<<(GV * F_DIM + 255) / 256, 256>>>(W);
    prep_split_x<<<(BT_N * F_DIM + 255) / 256, 256>>>(x);
    prep_misc<<<1, 256>>>(mask);

    dim3 ggrid(GV / BN, BT_N / BM);   // (128, 32)
    gemm_kernel<<<ggrid, 128, GEMM_SMEM>>>(bias, u, emb);

    combine_kernel<<<BT_N * 2, 32>>>(mask, out);

    dim3 mgrid(GV / 512, 16);
    marg_kernel<<<mgrid, 256>>>();

    final_kernel<<<1, 256>>>(out);
}

// round 12
// speedup vs baseline: 1.7502x; 1.1565x over previous
#include <cuda_runtime.h>
#include <cuda_fp16.h>
#include <cuda_bf16.h>
#include <cstdint>
#include <cstddef>

// ---------------- problem constants ----------------
#define BT_N   4096      // B*T
#define F_DIM  256
#define GV     16384     // G*V
#define V_DIM  8192
#define DG     8
#define KK     768       // 3 * F_DIM  (fp16-split GEMM packed along K)

// ---------------- scratch (device globals; no runtime allocation) ----------------
__device__ __half g_E[(size_t)BT_N * GV];               // 134 MB: exp(h) fp16 for marginal
__device__ float  g_part[(size_t)BT_N * 128 * 16];      // 33.5 MB per-(row,tile) partials
__device__ __half g_Asplit[(size_t)BT_N * KK];          // [xh | xh | xl]
__device__ __half g_Bsplit[(size_t)GV   * KK];          // [Wh | Wl | Wh]
__device__ float  g_R[BT_N * 2];                        // mask*inv_msum/Z per (bt,g)
__device__ float  g_marg[GV];                           // marginal accumulator
__device__ float  g_inv_msum;

// ---------------- FFMA log (final kernel) + exp ----------------
__device__ __forceinline__ float my_logf(float a) {
    float m, r, s, t, i, f;
    int e;
    e = (__float_as_int(a) - 0x3f2aaaab) & 0xff800000;
    m = __int_as_float(__float_as_int(a) - e);
    i = (float)e * 1.19209290e-7f;
    f = m - 1.0f;
    s = f * f;
    r = -0.130310059f;
    t =  0.140869141f;
    r = fmaf(r, s, -0.121483512f);
    t = fmaf(t, s,  0.139814854f);
    r = fmaf(r, s, -0.166846126f);
    t = fmaf(t, s,  0.200120345f);
    r = fmaf(r, s, -0.249996200f);
    r = fmaf(t, f, r);
    r = fmaf(r, f,  0.333331972f);
    r = fmaf(r, f, -0.500000000f);
    r = fmaf(r, s, f);
    r = fmaf(i, 0.693147182f, r);
    return r;
}

__device__ __forceinline__ float my_expf(float a) {
    float f, r, j;
    int i;
    j = fmaf(1.442695041f, a, 12582912.f) - 12582912.f;
    f = fmaf(j, -6.93145752e-1f, a);
    f = fmaf(j, -1.42860677e-6f, f);
    i = (int)j;
    r = 1.37805939e-3f;
    r = fmaf(r, f, 8.37312452e-3f);
    r = fmaf(r, f, 4.16695364e-2f);
    r = fmaf(r, f, 1.66664720e-1f);
    r = fmaf(r, f, 4.99999851e-1f);
    r = fmaf(r, f, 1.00000000e+0f);
    r = fmaf(r, f, 1.00000000e+0f);
    r = __int_as_float(__float_as_int(r) + (i << 23));
    return r;
}

// inner = -log(u); hybrid: MUFU for u<0.875, exact-f log1p Taylor for u>=0.875.
__device__ __forceinline__ float neg_log_u(float uu) {
    uu = fmaxf(uu, 1.17549435e-38f);
    float inner_m = -__logf(uu);
    float f = uu - 1.0f;                       // exact for uu >= 0.5 (Sterbenz)
    float q = fmaf(f, -0.125f, 0.14285714f);   // log1p Taylor deg 7
    q = fmaf(q, f, -0.16666667f);
    q = fmaf(q, f,  0.20f);
    q = fmaf(q, f, -0.25f);
    q = fmaf(q, f,  0.33333333f);
    q = fmaf(q, f, -0.5f);
    q = fmaf(q, f,  1.0f);
    float inner_p = -(f * q);
    return (uu >= 0.875f) ? inner_p : inner_m;
}

// ---------------- prep kernels ----------------
__global__ void prep_split_w(const float* __restrict__ W) {
    int idx = blockIdx.x * blockDim.x + threadIdx.x;
    if (idx >= GV * F_DIM) return;
    int n = idx >> 8, k = idx & 255;
    float w = W[idx];
    __half hi = __float2half_rn(w);
    __half lo = __float2half_rn(w - __half2float(hi));
    size_t base = (size_t)n * KK;
    g_Bsplit[base + k]        = hi;
    g_Bsplit[base + 256 + k]  = lo;
    g_Bsplit[base + 512 + k]  = hi;
}

__global__ void prep_split_x(const float* __restrict__ X) {
    int idx = blockIdx.x * blockDim.x + threadIdx.x;
    if (idx >= BT_N * F_DIM) return;
    int n = idx >> 8, k = idx & 255;
    float x = X[idx];
    __half hi = __float2half_rn(x);
    __half lo = __float2half_rn(x - __half2float(hi));
    size_t base = (size_t)n * KK;
    g_Asplit[base + k]        = hi;
    g_Asplit[base + 256 + k]  = hi;
    g_Asplit[base + 512 + k]  = lo;
}

__global__ void prep_misc(const int* __restrict__ mask) {
    int t = threadIdx.x;
    for (int i = t; i < GV; i += 256) g_marg[i] = 0.f;
    int s = 0;
    for (int i = t; i < BT_N; i += 256) s += mask[i];
    __shared__ int sm[256];
    sm[t] = s; __syncthreads();
    for (int o = 128; o; o >>= 1) { if (t < o) sm[t] += sm[t + o]; __syncthreads(); }
    if (t == 0) g_inv_msum = 1.0f / (float)sm[0];
}

// ---------------- fused GEMM + epilogue ----------------
// Block tile 128x128, 4 warps, warp tile 64x64, BK=64, 3 stages, 2 CTAs/SM.
// Epilogue v5: U prefetched into freed stages (R11); ey stored as bf16 into
// dead stage2; sy/argmax/sh reduced in fp32 in phase 1; cv computed by
// bf16 mma.sync against a transposed emb tile (prefetched at kernel start).
#define BM 128
#define BN 128
#define BK 64
#define STAGES 3
#define A_BYTES  (BM * BK * 2)          // 16384
#define STG_BYTES (2 * A_BYTES)         // 32768
#define EY_OFF   (2 * STG_BYTES)        // stage2: 128x128 bf16 = 32768
#define EMBF_OFF (3 * STG_BYTES)        // 98304: emb fp32 tile 128x8 = 4096
#define EMBT_OFF (EMBF_OFF + 4096)      // embT bf16 8x128 (swizzled) = 2048
#define RED_OFF  (EMBT_OFF + 2048)      // 128 x 2 x float4 = 4096
#define CVS_OFF  0                      // cv scratch in dead U region (4KB)
#define GEMM_SMEM (RED_OFF + 4096)      // 108544

// swizzled byte offset of float2 (row r, col-pair c2) within the 64KB U region
#define USWZ(r, c2) ((r) * 512 + ((((c2) >> 1) ^ ((r) & 7)) << 4) + (((c2) & 1) << 3))
// swizzled byte offset within a 256B-row bf16 tile (chunk = 16B unit index 0..15)
#define BSWZ(r, chunk) ((r) * 256 + (((chunk) ^ ((r) & 7)) << 4))

__global__ void __launch_bounds__(128, 2) gemm_kernel(
    const float* __restrict__ bias, const float* __restrict__ U,
    const float* __restrict__ emb)
{
    extern __shared__ __align__(128) char smem[];
    int tid  = threadIdx.x;
    int lane = tid & 31, warp = tid >> 5;
    int wm = warp >> 1, wn = warp & 1;        // 2 x 2 warp grid, warp tile 64x64
    int bm = blockIdx.y, bn = blockIdx.x;
    const __half* gA = g_Asplit + (size_t)bm * BM * KK;
    const __half* gB = g_Bsplit + (size_t)bn * BN * KK;

    const int g  = bn >> 6;
    const int v0 = (bn & 63) * 128;

    auto load_stage = [&](int s, int kt) {
        int k0 = kt * BK;
        char* sa = smem + s * STG_BYTES;
        char* sb = sa + A_BYTES;
        #pragma unroll
        for (int i = 0; i < 8; i++) {
            int idx = tid + 128 * i;       // 0..1023
            int row = idx >> 3, c16 = idx & 7;
            int pc  = c16 ^ (row & 7);
            uint32_t da = (uint32_t)__cvta_generic_to_shared(sa + row * 128 + pc * 16);
            asm volatile("cp.async.cg.shared.global [%0], [%1], 16;\n"
                :: "r"(da), "l"(gA + (size_t)row * KK + k0 + c16 * 8));
            uint32_t db = (uint32_t)__cvta_generic_to_shared(sb + row * 128 + pc * 16);
            asm volatile("cp.async.cg.shared.global [%0], [%1], 16;\n"
                :: "r"(db), "l"(gB + (size_t)row * KK + k0 + c16 * 8));
        }
    };

    // prefetch half of the U tile (64 rows x 128 cols fp32 = 32KB) into a freed stage
    auto load_u_half = [&](int half) {
        const float* Ub = U + (size_t)(bm * BM + half * 64) * GV + bn * BN;
        char* dstbase = smem + half * STG_BYTES;   // stage 'half' (0 or 1)
        #pragma unroll
        for (int i = 0; i < 16; i++) {
            int idx = tid + 128 * i;       // 0..2047 chunks
            int rr = idx >> 5, cc = idx & 31;   // rr 0..63 (local), cc chunk 0..31
            uint32_t d = (uint32_t)__cvta_generic_to_shared(
                dstbase + rr * 512 + ((cc ^ (rr & 7)) << 4));
            asm volatile("cp.async.cg.shared.global [%0], [%1], 16;\n"
                :: "r"(d), "l"(Ub + (size_t)rr * GV + cc * 4));
        }
    };

    // prefetch the emb tile (128 v x 8 d fp32 = 4KB) to EMBF (region untouched by mainloop)
    {
        const float* eb = emb + ((size_t)g * V_DIM + v0) * DG;
        #pragma unroll
        for (int i = 0; i < 2; i++) {
            int idx = tid * 2 + i;         // 0..255 16B chunks
            uint32_t d = (uint32_t)__cvta_generic_to_shared(smem + EMBF_OFF + idx * 16);
            asm volatile("cp.async.cg.shared.global [%0], [%1], 16;\n"
                :: "r"(d), "l"(eb + idx * 4));
        }
    }

    float acc[4][8][4];
    #pragma unroll
    for (int a = 0; a < 4; a++)
        #pragma unroll
        for (int b = 0; b < 8; b++)
            #pragma unroll
            for (int c = 0; c < 4; c++) acc[a][b][c] = 0.f;

    const int NKT = KK / BK;  // 12
    #pragma unroll
    for (int kt = 0; kt < STAGES - 1; kt++) {
        load_stage(kt, kt);
        asm volatile("cp.async.commit_group;\n");
    }

    #pragma unroll 1
    for (int kt = 0; kt < NKT; kt++) {
        asm volatile("cp.async.wait_group 1;\n");
        __syncthreads();
        int pf = kt + STAGES - 1;
        if (pf < NKT) {
            load_stage(pf % STAGES, pf);
        } else {
            load_u_half(pf - NKT);   // kt=10 -> U rows 0-63, kt=11 -> rows 64-127
        }
        asm volatile("cp.async.commit_group;\n");

        int s = kt % STAGES;
        const char* sa = smem + s * STG_BYTES;
        const char* sb = sa + A_BYTES;
        #pragma unroll
        for (int kk = 0; kk < 4; kk++) {
            uint32_t a[4][4], b[8][2];
            int c16 = kk * 2 + (lane >> 4);
            #pragma unroll
            for (int mt = 0; mt < 4; mt++) {
                int row = wm * 64 + mt * 16 + (lane & 15);
                int pc  = c16 ^ (row & 7);
                uint32_t addr = (uint32_t)__cvta_generic_to_shared(sa + row * 128 + pc * 16);
                asm volatile("ldmatrix.sync.aligned.m8n8.x4.shared.b16 {%0,%1,%2,%3}, [%4];\n"
                    : "=r"(a[mt][0]), "=r"(a[mt][1]), "=r"(a[mt][2]), "=r"(a[mt][3]) : "r"(addr));
            }
            #pragma unroll
            for (int nb = 0; nb < 4; nb++) {
                int row = wn * 64 + nb * 16 + (lane & 15);
                int pc  = c16 ^ (row & 7);
                uint32_t addr = (uint32_t)__cvta_generic_to_shared(sb + row * 128 + pc * 16);
                uint32_t r0, r1, r2, r3;
                asm volatile("ldmatrix.sync.aligned.m8n8.x4.shared.b16 {%0,%1,%2,%3}, [%4];\n"
                    : "=r"(r0), "=r"(r1), "=r"(r2), "=r"(r3) : "r"(addr));
                b[nb * 2][0]     = r0; b[nb * 2 + 1][0] = r1;
                b[nb * 2][1]     = r2; b[nb * 2 + 1][1] = r3;
            }
            #pragma unroll
            for (int mt = 0; mt < 4; mt++)
                #pragma unroll
                for (int nt = 0; nt < 8; nt++) {
                    asm volatile("mma.sync.aligned.m16n8k16.row.col.f32.f16.f16.f32 "
                        "{%0,%1,%2,%3}, {%4,%5,%6,%7}, {%8,%9}, {%0,%1,%2,%3};\n"
                        : "+f"(acc[mt][nt][0]), "+f"(acc[mt][nt][1]),
                          "+f"(acc[mt][nt][2]), "+f"(acc[mt][nt][3])
                        : "r"(a[mt][0]), "r"(a[mt][1]), "r"(a[mt][2]), "r"(a[mt][3]),
                          "r"(b[nt][0]), "r"(b[nt][1]));
                }
        }
    }

    // ---- epilogue v5 ----
    asm volatile("cp.async.wait_group 0;\n");
    __syncthreads();   // U in stages 0-1, embF resident, stage2 free for ey-bf16

    float* red = (float*)(smem + RED_OFF);   // [128 rows][2 wn][4]: sh, sy, max, idx

    // bias for this thread's 16 columns
    float2 bb[8];
    #pragma unroll
    for (int nt = 0; nt < 8; nt++) {
        int n = bn * BN + wn * 64 + nt * 8 + (lane & 3) * 2;
        bb[nt] = *(const float2*)(bias + n);
    }

    // phase 1: per (mt,ch) row group: e, ey, reductions, stores
    #pragma unroll
    for (int mt = 0; mt < 4; mt++) {
        #pragma unroll
        for (int ch = 0; ch < 2; ch++) {
            int row_l = wm * 64 + mt * 16 + (lane >> 2) + ch * 8;
            size_t gb = (size_t)(bm * BM + row_l) * GV + bn * BN;
            float shp = 0.f, syp = 0.f, mxv = -1e30f;
            int mxi = 0;
            #pragma unroll
            for (int nt = 0; nt < 8; nt++) {
                int col2 = wn * 32 + nt * 4 + (lane & 3);   // float2 index 0..63
                float2 uv = *(float2*)(smem + USWZ(row_l, col2));
                float h0 = acc[mt][nt][ch * 2 + 0] + bb[nt].x;
                float h1 = acc[mt][nt][ch * 2 + 1] + bb[nt].y;
                float e0 = __expf(h0), e1 = __expf(h1);
                shp += e0 + e1;
                *(__half2*)(&g_E[gb + col2 * 2]) = __floats2half2_rn(e0, e1);
                float ey0 = __fdividef(e0, neg_log_u(uv.x));
                float ey1 = __fdividef(e1, neg_log_u(uv.y));
                syp += ey0 + ey1;
                if (ey0 > mxv) { mxv = ey0; mxi = col2 * 2; }
                if (ey1 > mxv) { mxv = ey1; mxi = col2 * 2 + 1; }
                // bf16 store into ey tile (stage2), ldmatrix-compatible swizzle
                __nv_bfloat162 bf2 = __floats2bfloat162_rn(ey0, ey1);
                *(__nv_bfloat162*)(smem + EY_OFF + BSWZ(row_l, col2 >> 2) + (col2 & 3) * 4) = bf2;
            }
            // quad reductions (lanes of a quad hold the same row)
            #pragma unroll
            for (int o = 1; o <= 2; o <<= 1) {
                shp += __shfl_xor_sync(0xffffffffu, shp, o);
                syp += __shfl_xor_sync(0xffffffffu, syp, o);
                float omv = __shfl_xor_sync(0xffffffffu, mxv, o);
                int   omi = __shfl_xor_sync(0xffffffffu, mxi, o);
                if (omv > mxv || (omv == mxv && omi < mxi)) { mxv = omv; mxi = omi; }
            }
            if ((lane & 3) == 0) {
                *(float4*)(red + row_l * 8 + wn * 4) =
                    make_float4(shp, syp, mxv, (float)mxi);
            }
        }
    }

    // embT: transpose + convert emb tile to bf16 [d=0..7][v=0..127], swizzled
    {
        const float* ef = (const float*)(smem + EMBF_OFF) + tid * 8;  // v = tid
        float4 ea = ((const float4*)ef)[0], ebv = ((const float4*)ef)[1];
        float vals[8] = {ea.x, ea.y, ea.z, ea.w, ebv.x, ebv.y, ebv.z, ebv.w};
        int chunk = tid >> 3;
        #pragma unroll
        for (int d = 0; d < 8; d++) {
            *(__nv_bfloat16*)(smem + EMBT_OFF + BSWZ(d, chunk) + (tid & 7) * 2) =
                __float2bfloat16_rn(vals[d]);
        }
    }
    __syncthreads();

    // phase 2: cv via bf16 mma. warp handles m-tiles (warp*2, warp*2+1).
    {
        int mt0 = warp * 2;
        float ac[2][4] = {{0, 0, 0, 0}, {0, 0, 0, 0}};
        #pragma unroll
        for (int ks = 0; ks < 8; ks++) {
            uint32_t b0, b1;
            {
                int l = lane & 15;
                int d = l & 7, c = 2 * ks + ((l >> 3) & 1);
                uint32_t baddr = (uint32_t)__cvta_generic_to_shared(
                    smem + EMBT_OFF + BSWZ(d, c));
                asm volatile("ldmatrix.sync.aligned.m8n8.x2.shared.b16 {%0,%1}, [%2];\n"
                    : "=r"(b0), "=r"(b1) : "r"(baddr));
            }
            #pragma unroll
            for (int t = 0; t < 2; t++) {
                int row = (mt0 + t) * 16 + (lane & 15);
                int c16 = 2 * ks + (lane >> 4);
                uint32_t aaddr = (uint32_t)__cvta_generic_to_shared(
                    smem + EY_OFF + BSWZ(row, c16));
                uint32_t a0, a1, a2, a3;
                asm volatile("ldmatrix.sync.aligned.m8n8.x4.shared.b16 {%0,%1,%2,%3}, [%4];\n"
                    : "=r"(a0), "=r"(a1), "=r"(a2), "=r"(a3) : "r"(aaddr));
                asm volatile("mma.sync.aligned.m16n8k16.row.col.f32.bf16.bf16.f32 "
                    "{%0,%1,%2,%3}, {%4,%5,%6,%7}, {%8,%9}, {%0,%1,%2,%3};\n"
                    : "+f"(ac[t][0]), "+f"(ac[t][1]), "+f"(ac[t][2]), "+f"(ac[t][3])
                    : "r"(a0), "r"(a1), "r"(a2), "r"(a3), "r"(b0), "r"(b1));
            }
        }
        // scatter cv accumulators to cvsm [row][8]
        float* cvs = (float*)(smem + CVS_OFF);
        #pragma unroll
        for (int t = 0; t < 2; t++) {
            int row = (mt0 + t) * 16 + (lane >> 2);
            int d2 = (lane & 3) * 2;
            *(float2*)(cvs + row * 8 + d2)       = make_float2(ac[t][0], ac[t][1]);
            *(float2*)(cvs + (row + 8) * 8 + d2) = make_float2(ac[t][2], ac[t][3]);
        }
    }
    __syncthreads();

    // phase 3: thread = row; combine wn halves, write g_part
    {
        int row_l = tid;
        int m = bm * BM + row_l;
        float4 r0 = *(float4*)(red + row_l * 8);
        float4 r1 = *(float4*)(red + row_l * 8 + 4);
        float sh = r0.x + r1.x;
        float sy = r0.y + r1.y;
        float mxv = r0.z; float mxi = r0.w;
        if (r1.z > mxv || (r1.z == mxv && r1.w < mxi)) { mxv = r1.z; mxi = r1.w; }
        const float* cvs = (const float*)(smem + CVS_OFF) + row_l * 8;
        float4 c0 = ((const float4*)cvs)[0], c1 = ((const float4*)cvs)[1];
        float* P = g_part + ((size_t)m * 128 + bn) * 16;
        ((float4*)P)[0] = make_float4(sy, mxv, (float)v0 + mxi, sh);
        ((float4*)P)[1] = c0;
        ((float4*)P)[2] = c1;
    }
}

// ---------------- combine: reduce 64 tile-partials per (bt,g) ----------------
__global__ void __launch_bounds__(32) combine_kernel(
    const int* __restrict__ mask, float* __restrict__ out)
{
    int r = blockIdx.x;            // 0..8191
    int bt = r >> 1, gg = r & 1;
    int lane = threadIdx.x;
    const float* Pa = g_part + (((size_t)bt * 128) + gg * 64 + lane) * 16;
    const float* Pb = Pa + 32 * 16;
    float4 a0 = ((const float4*)Pa)[0], a1 = ((const float4*)Pa)[1], a2 = ((const float4*)Pa)[2];
    float4 b0 = ((const float4*)Pb)[0], b1 = ((const float4*)Pb)[1], b2 = ((const float4*)Pb)[2];
    float sy = a0.x + b0.x;
    float sh = a0.w + b0.w;
    float my = a0.y, vx = a0.z;
    if (b0.y > my || (b0.y == my && b0.z < vx)) { my = b0.y; vx = b0.z; }
    float cv[8];
    cv[0] = a1.x + b1.x; cv[1] = a1.y + b1.y; cv[2] = a1.z + b1.z; cv[3] = a1.w + b1.w;
    cv[4] = a2.x + b2.x; cv[5] = a2.y + b2.y; cv[6] = a2.z + b2.z; cv[7] = a2.w + b2.w;
    #pragma unroll
    for (int o = 16; o; o >>= 1) {
        sy += __shfl_xor_sync(0xffffffffu, sy, o);
        sh += __shfl_xor_sync(0xffffffffu, sh, o);
        float omy = __shfl_xor_sync(0xffffffffu, my, o);
        float ovx = __shfl_xor_sync(0xffffffffu, vx, o);
        if (omy > my || (omy == my && ovx < vx)) { my = omy; vx = ovx; }
        #pragma unroll
        for (int d = 0; d < 8; d++) cv[d] += __shfl_xor_sync(0xffffffffu, cv[d], o);
    }
    if (lane == 0) {
        float is = 1.f / sy;
        #pragma unroll
        for (int d = 0; d < 8; d++) out[bt * 16 + gg * 8 + d] = cv[d] * is;
        out[65537 + r] = vx;                                   // targets_idx
        g_R[r] = mask[bt] ? (g_inv_msum / sh) : 0.f;
    }
}

// ---------------- marginal column reduction (fp16 e, half2) ----------------
__global__ void __launch_bounds__(256) marg_kernel() {
    int c2 = blockIdx.x * 256 + threadIdx.x;   // 0..8191 column pairs
    int c  = c2 * 2;
    int g  = c >> 13;
    int bt0 = blockIdx.y * 256;
    float ax = 0.f, ay = 0.f;
    const __half2* Ep = (const __half2*)(g_E + (size_t)bt0 * GV + c);
    const float*   Rp = g_R + bt0 * 2 + g;
    #pragma unroll 4
    for (int i = 0; i < 256; ++i) {
        float2 e2 = __half22float2(*Ep);
        float r = *Rp;
        ax = fmaf(r, e2.x, ax);
        ay = fmaf(r, e2.y, ay);
        Ep += GV / 2;
        Rp += 2;
    }
    atomicAdd(&g_marg[c], ax);
    atomicAdd(&g_marg[c + 1], ay);
}

// ---------------- perplexity ----------------
__global__ void __launch_bounds__(256) final_kernel(float* __restrict__ out) {
    int t = threadIdx.x;
    float s0 = 0.f, s1v = 0.f;
    for (int c = t; c < V_DIM; c += 256) {
        float m = g_marg[c];
        s0 += m * my_logf(m + 1e-7f);
    }
    for (int c = V_DIM + t; c < GV; c += 256) {
        float m = g_marg[c];
        s1v += m * my_logf(m + 1e-7f);
    }
    __shared__ float sa[256], sb[256];
    sa[t] = s0; sb[t] = s1v; __syncthreads();
    for (int o = 128; o; o >>= 1) {
        if (t < o) { sa[t] += sa[t + o]; sb[t] += sb[t + o]; }
        __syncthreads();
    }
    if (t == 0) out[65536] = my_expf(-sa[0]) + my_expf(-sb[0]);
}

// ---------------- launch ----------------
extern "C" void kernel_launch(void* const* d_in, const int* in_sizes, int n_in,
                              void* d_out, int out_size) {
    const float* x    = (const float*)d_in[0];   // [8,512,256]
    const float* u    = (const float*)d_in[1];   // [8192, 8192]
    const float* emb  = (const float*)d_in[2];   // [1, 16384, 8]
    const float* W    = (const float*)d_in[3];   // [16384, 256]
    const float* bias = (const float*)d_in[4];   // [16384]
    const int*   mask = (const int*)d_in[5];     // [8,512]
    float* out = (float*)d_out;

    cudaFuncSetAttribute(gemm_kernel, cudaFuncAttributeMaxDynamicSharedMemorySize, GEMM_SMEM);

    prep_split_w<<<(GV * F_DIM + 255) / 256, 256>>>(W);
    prep_split_x<<<(BT_N * F_DIM + 255) / 256, 256>>>(x);
    prep_misc<<<1, 256>>>(mask);

    dim3 ggrid(GV / BN, BT_N / BM);   // (128, 32)
    gemm_kernel<<<ggrid, 128, GEMM_SMEM>>>(bias, u, emb);

    combine_kernel<<<BT_N * 2, 32>>>(mask, out);

    dim3 mgrid(GV / 512, 16);
    marg_kernel<<<mgrid, 256>>>();

    final_kernel<<<1, 256>>>(out);
}